// round 3
// baseline (speedup 1.0000x reference)
#include <cuda_runtime.h>
#include <cstdint>

#define NX 100000
#define NC 50000
#define NR 1000
#define HID 64
#define NTOT (NX + NC + NR)
#define EMAX 4100000

// Scratch (__device__ globals; no allocation allowed)
__device__ __align__(16) float g_h_all[NTOT * HID];   // 38.7 MB: [h_xx | h_cx | h_rx]
__device__ __align__(16) float g_self[NX * HID];      // 25.6 MB: relu(x@W_x^T+b_x)
__device__ __align__(16) float g_agg[NX * HID];       // 25.6 MB
__device__ int g_cnt[NX];                             // histogram, then cursor
__device__ int g_row[NX + 1];                         // CSR row offsets
__device__ int g_ssrc[EMAX];                          // dst-sorted src ids (global h_all row)

// ---------------------------------------------------------------------------
// Fused Linear (+optional ReLU): Y[N,64] = act(X[N,K] @ W[64,K]^T + b[64])
// 256 rows x 64 cols per block, 256 threads, 4x16 register tile per thread.
// ---------------------------------------------------------------------------
template <bool RELU>
__global__ void linear_kernel(const float* __restrict__ X,
                              const float* __restrict__ W,
                              const float* __restrict__ B,
                              float* __restrict__ Y,
                              int N, int K) {
    extern __shared__ float smem[];
    const int XS_STRIDE = K + 1;
    float* Xs = smem;                       // [256][K+1]
    float* Ws = smem + 256 * XS_STRIDE;     // [K][68]

    const int tid  = threadIdx.x;
    const int row0 = blockIdx.x * 256;

    for (int idx = tid; idx < 64 * K; idx += 256) {
        int j = idx / K;
        int k = idx - j * K;
        Ws[k * 68 + j] = W[idx];
    }
    for (int idx = tid; idx < 256 * K; idx += 256) {
        int r = idx / K;
        int k = idx - r * K;
        int gr = row0 + r;
        Xs[r * XS_STRIDE + k] = (gr < N) ? X[(size_t)gr * K + k] : 0.0f;
    }
    __syncthreads();

    const int cg = tid & 3;
    const int rg = tid >> 2;

    float acc[4][16];
#pragma unroll
    for (int i = 0; i < 4; ++i)
#pragma unroll
        for (int j = 0; j < 16; ++j) acc[i][j] = 0.0f;

    const float* wp = Ws + cg * 16;
    const float* xp = Xs + rg * 4 * XS_STRIDE;

#pragma unroll 4
    for (int k = 0; k < K; ++k) {
        float wv[16];
        *(float4*)(wv)      = *(const float4*)(wp + k * 68);
        *(float4*)(wv + 4)  = *(const float4*)(wp + k * 68 + 4);
        *(float4*)(wv + 8)  = *(const float4*)(wp + k * 68 + 8);
        *(float4*)(wv + 12) = *(const float4*)(wp + k * 68 + 12);
#pragma unroll
        for (int i = 0; i < 4; ++i) {
            float xv = xp[i * XS_STRIDE + k];
#pragma unroll
            for (int j = 0; j < 16; ++j) acc[i][j] += xv * wv[j];
        }
    }

    float bb[16];
    *(float4*)(bb)      = *(const float4*)(B + cg * 16);
    *(float4*)(bb + 4)  = *(const float4*)(B + cg * 16 + 4);
    *(float4*)(bb + 8)  = *(const float4*)(B + cg * 16 + 8);
    *(float4*)(bb + 12) = *(const float4*)(B + cg * 16 + 12);

#pragma unroll
    for (int i = 0; i < 4; ++i) {
        int gr = row0 + rg * 4 + i;
        if (gr >= N) continue;
        float o[16];
#pragma unroll
        for (int j = 0; j < 16; ++j) {
            float v = acc[i][j] + bb[j];
            o[j] = RELU ? (v > 0.0f ? v : 0.0f) : v;
        }
        float4* yp = (float4*)(Y + (size_t)gr * 64 + cg * 16);
        yp[0] = *(float4*)(o);
        yp[1] = *(float4*)(o + 4);
        yp[2] = *(float4*)(o + 8);
        yp[3] = *(float4*)(o + 12);
    }
}

// --------------------------- CSR build kernels -----------------------------
__global__ void hist_kernel(const int* __restrict__ dst, int E, int* __restrict__ cnt) {
    int e = blockIdx.x * blockDim.x + threadIdx.x;
    if (e < E) atomicAdd(&cnt[dst[e]], 1);
}

__global__ void scan_kernel(const int* __restrict__ cnt, int* __restrict__ row, int n) {
    __shared__ int part[1024];
    const int tid = threadIdx.x;
    const int chunk = (n + 1023) / 1024;
    int beg = tid * chunk;
    int end = beg + chunk; if (end > n) end = n;
    int s = 0;
    for (int i = beg; i < end; ++i) s += cnt[i];
    part[tid] = s;
    __syncthreads();
    for (int off = 1; off < 1024; off <<= 1) {
        int v = (tid >= off) ? part[tid - off] : 0;
        __syncthreads();
        part[tid] += v;
        __syncthreads();
    }
    int run = (tid > 0) ? part[tid - 1] : 0;
    for (int i = beg; i < end; ++i) { row[i] = run; run += cnt[i]; }
    if (tid == 1023) row[n] = part[1023];
}

__global__ void bin_kernel(const int* __restrict__ src, const int* __restrict__ dst,
                           int E, int base, int* __restrict__ cursor,
                           int* __restrict__ ssrc) {
    int e = blockIdx.x * blockDim.x + threadIdx.x;
    if (e >= E) return;
    int d = dst[e];
    int p = atomicAdd(&cursor[d], 1);
    ssrc[p] = src[e] + base;
}

// ---------------------------------------------------------------------------
// Gather-accumulate: agg[n] = self[n] + sum_{e in CSR(n)} h_all[ssrc[e]]
// 16 threads per node, float4 per lane. No atomics.
// ---------------------------------------------------------------------------
__global__ void gather_kernel(const float* __restrict__ h_all,
                              const float* __restrict__ self,
                              const int* __restrict__ row,
                              const int* __restrict__ ssrc,
                              float* __restrict__ agg) {
    int t = blockIdx.x * blockDim.x + threadIdx.x;
    int node = t >> 4;
    int lane = t & 15;
    if (node >= NX) return;
    float4 acc = ((const float4*)self)[(size_t)node * 16 + lane];
    int beg = row[node];
    int end = row[node + 1];
    for (int e = beg; e < end; ++e) {
        int s = ssrc[e];                       // broadcast within 16-lane group
        float4 v = ((const float4*)h_all)[(size_t)s * 16 + lane];
        acc.x += v.x; acc.y += v.y; acc.z += v.z; acc.w += v.w;
    }
    ((float4*)agg)[(size_t)node * 16 + lane] = acc;
}

extern "C" void kernel_launch(void* const* d_in, const int* in_sizes, int n_in,
                              void* d_out, int out_size) {
    const float* x      = (const float*)d_in[0];
    const float* c      = (const float*)d_in[1];
    const float* r      = (const float*)d_in[2];
    const int* e_xx_s   = (const int*)d_in[3];
    const int* e_xx_d   = (const int*)d_in[4];
    const int* e_cx_s   = (const int*)d_in[5];
    const int* e_cx_d   = (const int*)d_in[6];
    const int* e_rx_s   = (const int*)d_in[7];
    const int* e_rx_d   = (const int*)d_in[8];
    const float* W_x    = (const float*)d_in[9];
    const float* b_x    = (const float*)d_in[10];
    const float* W_c    = (const float*)d_in[11];
    const float* b_c    = (const float*)d_in[12];
    const float* W_r    = (const float*)d_in[13];
    const float* b_r    = (const float*)d_in[14];
    const float* W_xx   = (const float*)d_in[15];
    const float* b_xx   = (const float*)d_in[16];
    const float* W_cx   = (const float*)d_in[17];
    const float* b_cx   = (const float*)d_in[18];
    const float* W_rx   = (const float*)d_in[19];
    const float* b_rx   = (const float*)d_in[20];
    const float* W_pool = (const float*)d_in[21];
    const float* b_pool = (const float*)d_in[22];
    float* out = (float*)d_out;

    const int E_xx = in_sizes[3];
    const int E_cx = in_sizes[5];
    const int E_rx = in_sizes[7];

    void* p;
    cudaGetSymbolAddress(&p, g_h_all); float* h_all = (float*)p;
    cudaGetSymbolAddress(&p, g_self);  float* hself = (float*)p;
    cudaGetSymbolAddress(&p, g_agg);   float* agg   = (float*)p;
    cudaGetSymbolAddress(&p, g_cnt);   int*   cnt   = (int*)p;
    cudaGetSymbolAddress(&p, g_row);   int*   row   = (int*)p;
    cudaGetSymbolAddress(&p, g_ssrc);  int*   ssrc  = (int*)p;

    const int shb64 = (256 * 65 + 64 * 68) * 4;
    const int shb32 = (256 * 33 + 32 * 68) * 4;
    const int shb48 = (256 * 49 + 48 * 68) * 4;
    cudaFuncSetAttribute((const void*)linear_kernel<true>,
                         cudaFuncAttributeMaxDynamicSharedMemorySize, shb64);
    cudaFuncSetAttribute((const void*)linear_kernel<false>,
                         cudaFuncAttributeMaxDynamicSharedMemorySize, shb64);

    const int OFF_C = NX * 64;
    const int OFF_R = NX * 64 + NC * 64;

    dim3 blk(256);
    int gx = (NX + 255) / 256;
    int gc = (NC + 255) / 256;
    int gr = (NR + 255) / 256;

    // --- CSR build (independent of GEMMs; front-loaded) ---
    cudaMemsetAsync(cnt, 0, NX * sizeof(int));
    hist_kernel<<<(E_xx + 255) / 256, blk>>>(e_xx_d, E_xx, cnt);
    hist_kernel<<<(E_cx + 255) / 256, blk>>>(e_cx_d, E_cx, cnt);
    hist_kernel<<<(E_rx + 255) / 256, blk>>>(e_rx_d, E_rx, cnt);
    scan_kernel<<<1, 1024>>>(cnt, row, NX);
    cudaMemcpyAsync(cnt, row, NX * sizeof(int), cudaMemcpyDeviceToDevice);
    bin_kernel<<<(E_xx + 255) / 256, blk>>>(e_xx_s, e_xx_d, E_xx, 0,        cnt, ssrc);
    bin_kernel<<<(E_cx + 255) / 256, blk>>>(e_cx_s, e_cx_d, E_cx, NX,       cnt, ssrc);
    bin_kernel<<<(E_rx + 255) / 256, blk>>>(e_rx_s, e_rx_d, E_rx, NX + NC,  cnt, ssrc);

    // --- Node-level fused Linear+ReLU ---
    linear_kernel<true><<<gx, blk, shb64>>>(x, W_x,  b_x,  hself,                 NX, 64);
    linear_kernel<true><<<gx, blk, shb64>>>(x, W_xx, b_xx, h_all,                 NX, 64);
    linear_kernel<true><<<gc, blk, shb32>>>(c, W_cx, b_cx, h_all + (size_t)NX*64, NC, 32);
    linear_kernel<true><<<gr, blk, shb48>>>(r, W_rx, b_rx, h_all + (size_t)(NX+NC)*64, NR, 48);
    linear_kernel<true><<<gc, blk, shb32>>>(c, W_c,  b_c,  out + OFF_C,           NC, 32);
    linear_kernel<true><<<gr, blk, shb48>>>(r, W_r,  b_r,  out + OFF_R,           NR, 48);

    // --- CSR gather-accumulate (no atomics) ---
    {
        long long t = (long long)NX * 16;
        gather_kernel<<<(unsigned)((t + 255) / 256), blk>>>(h_all, hself, row, ssrc, agg);
    }

    // --- Pool GEMM ---
    linear_kernel<false><<<gx, blk, shb64>>>(agg, W_pool, b_pool, out, NX, 64);
}

// round 5
// speedup vs baseline: 1.2256x; 1.2256x over previous
#include <cuda_runtime.h>
#include <cstdint>

#define NX 100000
#define NC 50000
#define NR 1000
#define HID 64
#define NTOT (NX + NC + NR)
#define EMAX 4100000

#define SCAN_CHUNK 512
#define SCAN_NBLK ((NX + SCAN_CHUNK - 1) / SCAN_CHUNK)   // 196

// Scratch (__device__ globals; no allocation allowed)
__device__ __align__(16) float g_h_all[NTOT * HID];   // 38.7 MB
__device__ __align__(16) float g_self[NX * HID];      // 25.6 MB
__device__ __align__(16) float g_agg[NX * HID];       // 25.6 MB
__device__ int g_cnt[NX];
__device__ int g_row[NX + 1];
__device__ int g_bsum[SCAN_NBLK];
__device__ int g_boff[SCAN_NBLK];
__device__ int g_ssrc[EMAX];

// ---------------------------------------------------------------------------
// Fused Linear (+optional ReLU): Y[N,64] = act(X[N,K] @ W[64,K]^T + b[64])
// ---------------------------------------------------------------------------
template <bool RELU>
__global__ void linear_kernel(const float* __restrict__ X,
                              const float* __restrict__ W,
                              const float* __restrict__ B,
                              float* __restrict__ Y,
                              int N, int K) {
    extern __shared__ float smem[];
    const int XS_STRIDE = K + 1;
    float* Xs = smem;                       // [256][K+1]
    float* Ws = smem + 256 * XS_STRIDE;     // [K][68]

    const int tid  = threadIdx.x;
    const int row0 = blockIdx.x * 256;

    for (int idx = tid; idx < 64 * K; idx += 256) {
        int j = idx / K;
        int k = idx - j * K;
        Ws[k * 68 + j] = W[idx];
    }
    for (int idx = tid; idx < 256 * K; idx += 256) {
        int r = idx / K;
        int k = idx - r * K;
        int gr = row0 + r;
        Xs[r * XS_STRIDE + k] = (gr < N) ? X[(size_t)gr * K + k] : 0.0f;
    }
    __syncthreads();

    const int cg = tid & 3;
    const int rg = tid >> 2;

    float acc[4][16];
#pragma unroll
    for (int i = 0; i < 4; ++i)
#pragma unroll
        for (int j = 0; j < 16; ++j) acc[i][j] = 0.0f;

    const float* wp = Ws + cg * 16;
    const float* xp = Xs + rg * 4 * XS_STRIDE;

#pragma unroll 4
    for (int k = 0; k < K; ++k) {
        float wv[16];
        *(float4*)(wv)      = *(const float4*)(wp + k * 68);
        *(float4*)(wv + 4)  = *(const float4*)(wp + k * 68 + 4);
        *(float4*)(wv + 8)  = *(const float4*)(wp + k * 68 + 8);
        *(float4*)(wv + 12) = *(const float4*)(wp + k * 68 + 12);
#pragma unroll
        for (int i = 0; i < 4; ++i) {
            float xv = xp[i * XS_STRIDE + k];
#pragma unroll
            for (int j = 0; j < 16; ++j) acc[i][j] += xv * wv[j];
        }
    }

    float bb[16];
    *(float4*)(bb)      = *(const float4*)(B + cg * 16);
    *(float4*)(bb + 4)  = *(const float4*)(B + cg * 16 + 4);
    *(float4*)(bb + 8)  = *(const float4*)(B + cg * 16 + 8);
    *(float4*)(bb + 12) = *(const float4*)(B + cg * 16 + 12);

#pragma unroll
    for (int i = 0; i < 4; ++i) {
        int gr = row0 + rg * 4 + i;
        if (gr >= N) continue;
        float o[16];
#pragma unroll
        for (int j = 0; j < 16; ++j) {
            float v = acc[i][j] + bb[j];
            o[j] = RELU ? (v > 0.0f ? v : 0.0f) : v;
        }
        float4* yp = (float4*)(Y + (size_t)gr * 64 + cg * 16);
        yp[0] = *(float4*)(o);
        yp[1] = *(float4*)(o + 4);
        yp[2] = *(float4*)(o + 8);
        yp[3] = *(float4*)(o + 12);
    }
}

// --------------------------- CSR build kernels -----------------------------
__global__ void hist_kernel(const int* __restrict__ dst, int E, int* __restrict__ cnt) {
    int e = blockIdx.x * blockDim.x + threadIdx.x;
    if (e < E) atomicAdd(&cnt[dst[e]], 1);
}

// Multi-block exclusive scan of cnt[NX] -> row[NX] (+row[NX]=total), 3 phases.
__global__ void scan_reduce_kernel(const int* __restrict__ cnt, int n,
                                   int* __restrict__ bsum) {
    __shared__ int sh[SCAN_CHUNK];
    int g = blockIdx.x * SCAN_CHUNK + threadIdx.x;
    int v = (g < n) ? cnt[g] : 0;
    sh[threadIdx.x] = v;
    __syncthreads();
    for (int off = SCAN_CHUNK / 2; off > 0; off >>= 1) {
        if (threadIdx.x < off) sh[threadIdx.x] += sh[threadIdx.x + off];
        __syncthreads();
    }
    if (threadIdx.x == 0) bsum[blockIdx.x] = sh[0];
}

__global__ void scan_partials_kernel(const int* __restrict__ bsum,
                                     int* __restrict__ boff,
                                     int* __restrict__ row, int n) {
    __shared__ int sh[256];
    int tid = threadIdx.x;
    int v = (tid < SCAN_NBLK) ? bsum[tid] : 0;
    sh[tid] = v;
    __syncthreads();
    for (int off = 1; off < 256; off <<= 1) {
        int t = (tid >= off) ? sh[tid - off] : 0;
        __syncthreads();
        sh[tid] += t;
        __syncthreads();
    }
    if (tid < SCAN_NBLK) boff[tid] = sh[tid] - v;   // exclusive
    if (tid == 255) row[n] = sh[255];               // total edge count
}

__global__ void scan_final_kernel(const int* __restrict__ cnt, int n,
                                  const int* __restrict__ boff,
                                  int* __restrict__ row) {
    __shared__ int sh[SCAN_CHUNK];
    int tid = threadIdx.x;
    int g = blockIdx.x * SCAN_CHUNK + tid;
    int v = (g < n) ? cnt[g] : 0;
    sh[tid] = v;
    __syncthreads();
    // Hillis-Steele inclusive scan
    for (int off = 1; off < SCAN_CHUNK; off <<= 1) {
        int t = (tid >= off) ? sh[tid - off] : 0;
        __syncthreads();
        sh[tid] += t;
        __syncthreads();
    }
    if (g < n) row[g] = boff[blockIdx.x] + sh[tid] - v;   // exclusive
}

__global__ void bin_kernel(const int* __restrict__ src, const int* __restrict__ dst,
                           int E, int base, int* __restrict__ cursor,
                           int* __restrict__ ssrc) {
    int e = blockIdx.x * blockDim.x + threadIdx.x;
    if (e >= E) return;
    int d = dst[e];
    int p = atomicAdd(&cursor[d], 1);
    ssrc[p] = src[e] + base;
}

// ---------------------------------------------------------------------------
// Gather-accumulate: agg[n] = self[n] + sum_{e in CSR(n)} h_all[ssrc[e]]
// ---------------------------------------------------------------------------
__global__ void gather_kernel(const float* __restrict__ h_all,
                              const float* __restrict__ self,
                              const int* __restrict__ row,
                              const int* __restrict__ ssrc,
                              float* __restrict__ agg) {
    int t = blockIdx.x * blockDim.x + threadIdx.x;
    int node = t >> 4;
    int lane = t & 15;
    if (node >= NX) return;
    float4 acc = ((const float4*)self)[(size_t)node * 16 + lane];
    int beg = row[node];
    int end = row[node + 1];
    for (int e = beg; e < end; ++e) {
        int s = ssrc[e];
        float4 v = ((const float4*)h_all)[(size_t)s * 16 + lane];
        acc.x += v.x; acc.y += v.y; acc.z += v.z; acc.w += v.w;
    }
    ((float4*)agg)[(size_t)node * 16 + lane] = acc;
}

extern "C" void kernel_launch(void* const* d_in, const int* in_sizes, int n_in,
                              void* d_out, int out_size) {
    const float* x      = (const float*)d_in[0];
    const float* c      = (const float*)d_in[1];
    const float* r      = (const float*)d_in[2];
    const int* e_xx_s   = (const int*)d_in[3];
    const int* e_xx_d   = (const int*)d_in[4];
    const int* e_cx_s   = (const int*)d_in[5];
    const int* e_cx_d   = (const int*)d_in[6];
    const int* e_rx_s   = (const int*)d_in[7];
    const int* e_rx_d   = (const int*)d_in[8];
    const float* W_x    = (const float*)d_in[9];
    const float* b_x    = (const float*)d_in[10];
    const float* W_c    = (const float*)d_in[11];
    const float* b_c    = (const float*)d_in[12];
    const float* W_r    = (const float*)d_in[13];
    const float* b_r    = (const float*)d_in[14];
    const float* W_xx   = (const float*)d_in[15];
    const float* b_xx   = (const float*)d_in[16];
    const float* W_cx   = (const float*)d_in[17];
    const float* b_cx   = (const float*)d_in[18];
    const float* W_rx   = (const float*)d_in[19];
    const float* b_rx   = (const float*)d_in[20];
    const float* W_pool = (const float*)d_in[21];
    const float* b_pool = (const float*)d_in[22];
    float* out = (float*)d_out;

    const int E_xx = in_sizes[3];
    const int E_cx = in_sizes[5];
    const int E_rx = in_sizes[7];

    void* p;
    cudaGetSymbolAddress(&p, g_h_all); float* h_all = (float*)p;
    cudaGetSymbolAddress(&p, g_self);  float* hself = (float*)p;
    cudaGetSymbolAddress(&p, g_agg);   float* agg   = (float*)p;
    cudaGetSymbolAddress(&p, g_cnt);   int*   cnt   = (int*)p;
    cudaGetSymbolAddress(&p, g_row);   int*   row   = (int*)p;
    cudaGetSymbolAddress(&p, g_bsum);  int*   bsum  = (int*)p;
    cudaGetSymbolAddress(&p, g_boff);  int*   boff  = (int*)p;
    cudaGetSymbolAddress(&p, g_ssrc);  int*   ssrc  = (int*)p;

    const int shb64 = (256 * 65 + 64 * 68) * 4;
    const int shb32 = (256 * 33 + 32 * 68) * 4;
    const int shb48 = (256 * 49 + 48 * 68) * 4;
    cudaFuncSetAttribute((const void*)linear_kernel<true>,
                         cudaFuncAttributeMaxDynamicSharedMemorySize, shb64);
    cudaFuncSetAttribute((const void*)linear_kernel<false>,
                         cudaFuncAttributeMaxDynamicSharedMemorySize, shb64);

    const int OFF_C = NX * 64;
    const int OFF_R = NX * 64 + NC * 64;

    dim3 blk(256);
    int gx = (NX + 255) / 256;
    int gc = (NC + 255) / 256;
    int gr = (NR + 255) / 256;

    // --- CSR build ---
    cudaMemsetAsync(cnt, 0, NX * sizeof(int));
    hist_kernel<<<(E_xx + 255) / 256, blk>>>(e_xx_d, E_xx, cnt);
    hist_kernel<<<(E_cx + 255) / 256, blk>>>(e_cx_d, E_cx, cnt);
    hist_kernel<<<(E_rx + 255) / 256, blk>>>(e_rx_d, E_rx, cnt);
    scan_reduce_kernel<<<SCAN_NBLK, SCAN_CHUNK>>>(cnt, NX, bsum);
    scan_partials_kernel<<<1, 256>>>(bsum, boff, row, NX);
    scan_final_kernel<<<SCAN_NBLK, SCAN_CHUNK>>>(cnt, NX, boff, row);
    cudaMemcpyAsync(cnt, row, NX * sizeof(int), cudaMemcpyDeviceToDevice);
    bin_kernel<<<(E_xx + 255) / 256, blk>>>(e_xx_s, e_xx_d, E_xx, 0,        cnt, ssrc);
    bin_kernel<<<(E_cx + 255) / 256, blk>>>(e_cx_s, e_cx_d, E_cx, NX,       cnt, ssrc);
    bin_kernel<<<(E_rx + 255) / 256, blk>>>(e_rx_s, e_rx_d, E_rx, NX + NC,  cnt, ssrc);

    // --- Node-level fused Linear+ReLU ---
    linear_kernel<true><<<gx, blk, shb64>>>(x, W_x,  b_x,  hself,                 NX, 64);
    linear_kernel<true><<<gx, blk, shb64>>>(x, W_xx, b_xx, h_all,                 NX, 64);
    linear_kernel<true><<<gc, blk, shb32>>>(c, W_cx, b_cx, h_all + (size_t)NX*64, NC, 32);
    linear_kernel<true><<<gr, blk, shb48>>>(r, W_rx, b_rx, h_all + (size_t)(NX+NC)*64, NR, 48);
    linear_kernel<true><<<gc, blk, shb32>>>(c, W_c,  b_c,  out + OFF_C,           NC, 32);
    linear_kernel<true><<<gr, blk, shb48>>>(r, W_r,  b_r,  out + OFF_R,           NR, 48);

    // --- CSR gather-accumulate (no atomics) ---
    {
        long long t = (long long)NX * 16;
        gather_kernel<<<(unsigned)((t + 255) / 256), blk>>>(h_all, hself, row, ssrc, agg);
    }

    // --- Pool GEMM ---
    linear_kernel<false><<<gx, blk, shb64>>>(agg, W_pool, b_pool, out, NX, 64);
}

// round 10
// speedup vs baseline: 1.5309x; 1.2491x over previous
#include <cuda_runtime.h>
#include <cstdint>

#define NX 100000
#define NC 50000
#define NR 1000
#define HID 64
#define NTOT (NX + NC + NR)
#define EMAX 4100000

#define SCAN_CHUNK 512
#define SCAN_NBLK ((NX + SCAN_CHUNK - 1) / SCAN_CHUNK)   // 196

// Scratch (__device__ globals; no allocation allowed)
__device__ __align__(16) float g_h_all[NTOT * HID];   // 38.7 MB
__device__ __align__(16) float g_self[NX * HID];      // 25.6 MB
__device__ __align__(16) float g_agg[NX * HID];       // 25.6 MB
__device__ int g_cnt[NX];
__device__ int g_row[NX + 1];
__device__ int g_bsum[SCAN_NBLK];
__device__ int g_boff[SCAN_NBLK];
__device__ int g_ssrc[EMAX];

// ---------------------------------------------------------------------------
// Fused Linear (+optional ReLU): Y[N,64] = act(X[N,K] @ W[64,K]^T + b[64])
// ---------------------------------------------------------------------------
template <bool RELU>
__global__ void linear_kernel(const float* __restrict__ X,
                              const float* __restrict__ W,
                              const float* __restrict__ B,
                              float* __restrict__ Y,
                              int N, int K) {
    extern __shared__ float smem[];
    const int XS_STRIDE = K + 1;
    float* Xs = smem;                       // [256][K+1]
    float* Ws = smem + 256 * XS_STRIDE;     // [K][68]

    const int tid  = threadIdx.x;
    const int row0 = blockIdx.x * 256;

    for (int idx = tid; idx < 64 * K; idx += 256) {
        int j = idx / K;
        int k = idx - j * K;
        Ws[k * 68 + j] = W[idx];
    }
    for (int idx = tid; idx < 256 * K; idx += 256) {
        int r = idx / K;
        int k = idx - r * K;
        int gr = row0 + r;
        Xs[r * XS_STRIDE + k] = (gr < N) ? X[(size_t)gr * K + k] : 0.0f;
    }
    __syncthreads();

    const int cg = tid & 3;
    const int rg = tid >> 2;

    float acc[4][16];
#pragma unroll
    for (int i = 0; i < 4; ++i)
#pragma unroll
        for (int j = 0; j < 16; ++j) acc[i][j] = 0.0f;

    const float* wp = Ws + cg * 16;
    const float* xp = Xs + rg * 4 * XS_STRIDE;

#pragma unroll 4
    for (int k = 0; k < K; ++k) {
        float wv[16];
        *(float4*)(wv)      = *(const float4*)(wp + k * 68);
        *(float4*)(wv + 4)  = *(const float4*)(wp + k * 68 + 4);
        *(float4*)(wv + 8)  = *(const float4*)(wp + k * 68 + 8);
        *(float4*)(wv + 12) = *(const float4*)(wp + k * 68 + 12);
#pragma unroll
        for (int i = 0; i < 4; ++i) {
            float xv = xp[i * XS_STRIDE + k];
#pragma unroll
            for (int j = 0; j < 16; ++j) acc[i][j] += xv * wv[j];
        }
    }

    float bb[16];
    *(float4*)(bb)      = *(const float4*)(B + cg * 16);
    *(float4*)(bb + 4)  = *(const float4*)(B + cg * 16 + 4);
    *(float4*)(bb + 8)  = *(const float4*)(B + cg * 16 + 8);
    *(float4*)(bb + 12) = *(const float4*)(B + cg * 16 + 12);

#pragma unroll
    for (int i = 0; i < 4; ++i) {
        int gr = row0 + rg * 4 + i;
        if (gr >= N) continue;
        float o[16];
#pragma unroll
        for (int j = 0; j < 16; ++j) {
            float v = acc[i][j] + bb[j];
            o[j] = RELU ? (v > 0.0f ? v : 0.0f) : v;
        }
        float4* yp = (float4*)(Y + (size_t)gr * 64 + cg * 16);
        yp[0] = *(float4*)(o);
        yp[1] = *(float4*)(o + 4);
        yp[2] = *(float4*)(o + 8);
        yp[3] = *(float4*)(o + 12);
    }
}

// --------------------------- CSR build kernels -----------------------------
__global__ void hist_kernel(const int* __restrict__ dst, int E, int* __restrict__ cnt) {
    int e = blockIdx.x * blockDim.x + threadIdx.x;
    if (e < E) atomicAdd(&cnt[dst[e]], 1);
}

__global__ void scan_reduce_kernel(const int* __restrict__ cnt, int n,
                                   int* __restrict__ bsum) {
    __shared__ int sh[SCAN_CHUNK];
    int g = blockIdx.x * SCAN_CHUNK + threadIdx.x;
    int v = (g < n) ? cnt[g] : 0;
    sh[threadIdx.x] = v;
    __syncthreads();
    for (int off = SCAN_CHUNK / 2; off > 0; off >>= 1) {
        if (threadIdx.x < off) sh[threadIdx.x] += sh[threadIdx.x + off];
        __syncthreads();
    }
    if (threadIdx.x == 0) bsum[blockIdx.x] = sh[0];
}

__global__ void scan_partials_kernel(const int* __restrict__ bsum,
                                     int* __restrict__ boff,
                                     int* __restrict__ row, int n) {
    __shared__ int sh[256];
    int tid = threadIdx.x;
    int v = (tid < SCAN_NBLK) ? bsum[tid] : 0;
    sh[tid] = v;
    __syncthreads();
    for (int off = 1; off < 256; off <<= 1) {
        int t = (tid >= off) ? sh[tid - off] : 0;
        __syncthreads();
        sh[tid] += t;
        __syncthreads();
    }
    if (tid < SCAN_NBLK) boff[tid] = sh[tid] - v;   // exclusive
    if (tid == 255) row[n] = sh[255];               // total
}

__global__ void scan_final_kernel(const int* __restrict__ cnt, int n,
                                  const int* __restrict__ boff,
                                  int* __restrict__ row) {
    __shared__ int sh[SCAN_CHUNK];
    int tid = threadIdx.x;
    int g = blockIdx.x * SCAN_CHUNK + tid;
    int v = (g < n) ? cnt[g] : 0;
    sh[tid] = v;
    __syncthreads();
    for (int off = 1; off < SCAN_CHUNK; off <<= 1) {
        int t = (tid >= off) ? sh[tid - off] : 0;
        __syncthreads();
        sh[tid] += t;
        __syncthreads();
    }
    if (g < n) row[g] = boff[blockIdx.x] + sh[tid] - v;   // exclusive
}

__global__ void bin_kernel(const int* __restrict__ src, const int* __restrict__ dst,
                           int E, int base, int* __restrict__ cursor,
                           int* __restrict__ ssrc) {
    int e = blockIdx.x * blockDim.x + threadIdx.x;
    if (e >= E) return;
    int d = dst[e];
    int p = atomicAdd(&cursor[d], 1);
    ssrc[p] = src[e] + base;
}

// ---------------------------------------------------------------------------
// Gather-accumulate: agg[n] = self[n] + sum_{e in CSR(n)} h_all[ssrc[e]]
// ---------------------------------------------------------------------------
__global__ void gather_kernel(const float* __restrict__ h_all,
                              const float* __restrict__ self,
                              const int* __restrict__ row,
                              const int* __restrict__ ssrc,
                              float* __restrict__ agg) {
    int t = blockIdx.x * blockDim.x + threadIdx.x;
    int node = t >> 4;
    int lane = t & 15;
    if (node >= NX) return;
    float4 acc = ((const float4*)self)[(size_t)node * 16 + lane];
    int beg = row[node];
    int end = row[node + 1];
    for (int e = beg; e < end; ++e) {
        int s = ssrc[e];
        float4 v = ((const float4*)h_all)[(size_t)s * 16 + lane];
        acc.x += v.x; acc.y += v.y; acc.z += v.z; acc.w += v.w;
    }
    ((float4*)agg)[(size_t)node * 16 + lane] = acc;
}

// ------------------------- stream/event singletons -------------------------
static cudaStream_t s_b = nullptr, s_c = nullptr;
static cudaEvent_t  ev_root = nullptr, ev_b = nullptr, ev_c = nullptr;

static void ensure_streams() {
    if (!s_b) {
        cudaStreamCreateWithFlags(&s_b, cudaStreamNonBlocking);
        cudaStreamCreateWithFlags(&s_c, cudaStreamNonBlocking);
        cudaEventCreateWithFlags(&ev_root, cudaEventDisableTiming);
        cudaEventCreateWithFlags(&ev_b,    cudaEventDisableTiming);
        cudaEventCreateWithFlags(&ev_c,    cudaEventDisableTiming);
    }
}

extern "C" void kernel_launch(void* const* d_in, const int* in_sizes, int n_in,
                              void* d_out, int out_size) {
    const float* x      = (const float*)d_in[0];
    const float* c      = (const float*)d_in[1];
    const float* r      = (const float*)d_in[2];
    const int* e_xx_s   = (const int*)d_in[3];
    const int* e_xx_d   = (const int*)d_in[4];
    const int* e_cx_s   = (const int*)d_in[5];
    const int* e_cx_d   = (const int*)d_in[6];
    const int* e_rx_s   = (const int*)d_in[7];
    const int* e_rx_d   = (const int*)d_in[8];
    const float* W_x    = (const float*)d_in[9];
    const float* b_x    = (const float*)d_in[10];
    const float* W_c    = (const float*)d_in[11];
    const float* b_c    = (const float*)d_in[12];
    const float* W_r    = (const float*)d_in[13];
    const float* b_r    = (const float*)d_in[14];
    const float* W_xx   = (const float*)d_in[15];
    const float* b_xx   = (const float*)d_in[16];
    const float* W_cx   = (const float*)d_in[17];
    const float* b_cx   = (const float*)d_in[18];
    const float* W_rx   = (const float*)d_in[19];
    const float* b_rx   = (const float*)d_in[20];
    const float* W_pool = (const float*)d_in[21];
    const float* b_pool = (const float*)d_in[22];
    float* out = (float*)d_out;

    const int E_xx = in_sizes[3];
    const int E_cx = in_sizes[5];
    const int E_rx = in_sizes[7];

    void* p;
    cudaGetSymbolAddress(&p, g_h_all); float* h_all = (float*)p;
    cudaGetSymbolAddress(&p, g_self);  float* hself = (float*)p;
    cudaGetSymbolAddress(&p, g_agg);   float* agg   = (float*)p;
    cudaGetSymbolAddress(&p, g_cnt);   int*   cnt   = (int*)p;
    cudaGetSymbolAddress(&p, g_row);   int*   row   = (int*)p;
    cudaGetSymbolAddress(&p, g_bsum);  int*   bsum  = (int*)p;
    cudaGetSymbolAddress(&p, g_boff);  int*   boff  = (int*)p;
    cudaGetSymbolAddress(&p, g_ssrc);  int*   ssrc  = (int*)p;

    ensure_streams();

    const int shb64 = (256 * 65 + 64 * 68) * 4;
    const int shb32 = (256 * 33 + 32 * 68) * 4;
    const int shb48 = (256 * 49 + 48 * 68) * 4;
    cudaFuncSetAttribute((const void*)linear_kernel<true>,
                         cudaFuncAttributeMaxDynamicSharedMemorySize, shb64);
    cudaFuncSetAttribute((const void*)linear_kernel<false>,
                         cudaFuncAttributeMaxDynamicSharedMemorySize, shb64);

    const int OFF_C = NX * 64;
    const int OFF_R = NX * 64 + NC * 64;

    dim3 blk(256);
    int gx = (NX + 255) / 256;
    int gc = (NC + 255) / 256;
    int gr = (NR + 255) / 256;

    // ---- fork: root event on legacy stream ----
    cudaEventRecord(ev_root, 0);
    cudaStreamWaitEvent(s_b, ev_root, 0);
    cudaStreamWaitEvent(s_c, ev_root, 0);

    // ---- stream B: CSR build chain ----
    cudaMemsetAsync(cnt, 0, NX * sizeof(int), s_b);
    hist_kernel<<<(E_xx + 255) / 256, blk, 0, s_b>>>(e_xx_d, E_xx, cnt);
    hist_kernel<<<(E_cx + 255) / 256, blk, 0, s_b>>>(e_cx_d, E_cx, cnt);
    hist_kernel<<<(E_rx + 255) / 256, blk, 0, s_b>>>(e_rx_d, E_rx, cnt);
    scan_reduce_kernel<<<SCAN_NBLK, SCAN_CHUNK, 0, s_b>>>(cnt, NX, bsum);
    scan_partials_kernel<<<1, 256, 0, s_b>>>(bsum, boff, row, NX);
    scan_final_kernel<<<SCAN_NBLK, SCAN_CHUNK, 0, s_b>>>(cnt, NX, boff, row);
    cudaMemcpyAsync(cnt, row, NX * sizeof(int), cudaMemcpyDeviceToDevice, s_b);
    bin_kernel<<<(E_xx + 255) / 256, blk, 0, s_b>>>(e_xx_s, e_xx_d, E_xx, 0,       cnt, ssrc);
    bin_kernel<<<(E_cx + 255) / 256, blk, 0, s_b>>>(e_cx_s, e_cx_d, E_cx, NX,      cnt, ssrc);
    bin_kernel<<<(E_rx + 255) / 256, blk, 0, s_b>>>(e_rx_s, e_rx_d, E_rx, NX + NC, cnt, ssrc);
    cudaEventRecord(ev_b, s_b);

    // ---- stream C: c/r GEMMs (small; includes two grid-4 NR kernels) ----
    linear_kernel<true><<<gc, blk, shb32, s_c>>>(c, W_cx, b_cx, h_all + (size_t)NX*64, NC, 32);
    linear_kernel<true><<<gr, blk, shb48, s_c>>>(r, W_rx, b_rx, h_all + (size_t)(NX+NC)*64, NR, 48);
    linear_kernel<true><<<gc, blk, shb32, s_c>>>(c, W_c,  b_c,  out + OFF_C, NC, 32);
    linear_kernel<true><<<gr, blk, shb48, s_c>>>(r, W_r,  b_r,  out + OFF_R, NR, 48);
    cudaEventRecord(ev_c, s_c);

    // ---- legacy stream: big x GEMMs ----
    linear_kernel<true><<<gx, blk, shb64>>>(x, W_x,  b_x,  hself, NX, 64);
    linear_kernel<true><<<gx, blk, shb64>>>(x, W_xx, b_xx, h_all, NX, 64);

    // ---- join ----
    cudaStreamWaitEvent(0, ev_b, 0);
    cudaStreamWaitEvent(0, ev_c, 0);

    // ---- gather + pool (serial tail) ----
    {
        long long t = (long long)NX * 16;
        gather_kernel<<<(unsigned)((t + 255) / 256), blk>>>(h_all, hself, row, ssrc, agg);
    }
    linear_kernel<false><<<gx, blk, shb64>>>(agg, W_pool, b_pool, out, NX, 64);
}

// round 11
// speedup vs baseline: 1.6837x; 1.0998x over previous
#include <cuda_runtime.h>
#include <cuda_fp16.h>
#include <cstdint>

#define NX 100000
#define NC 50000
#define NR 1000
#define HID 64
#define NTOT (NX + NC + NR)
#define EMAX 4100000

#define SCAN_CHUNK 512
#define SCAN_NBLK ((NX + SCAN_CHUNK - 1) / SCAN_CHUNK)   // 196

// Scratch (__device__ globals; no allocation allowed)
__device__ __align__(16) __half g_h_all[NTOT * HID];  // 19.4 MB (fp16 messages)
__device__ __align__(16) float g_self[NX * HID];      // 25.6 MB
__device__ __align__(16) float g_agg[NX * HID];       // 25.6 MB
__device__ int g_cnt[NX];
__device__ int g_row[NX + 1];
__device__ int g_bsum[SCAN_NBLK];
__device__ int g_boff[SCAN_NBLK];
__device__ int g_ssrc[EMAX];

// ---------------------------------------------------------------------------
// Fused Linear (+optional ReLU): Y[N,64] = act(X[N,K] @ W[64,K]^T + b[64])
// OutT = float (fp32 out) or __half (fp16 out, for the message buffer).
// ---------------------------------------------------------------------------
template <bool RELU, typename OutT>
__global__ void linear_kernel(const float* __restrict__ X,
                              const float* __restrict__ W,
                              const float* __restrict__ B,
                              OutT* __restrict__ Y,
                              int N, int K) {
    extern __shared__ float smem[];
    const int XS_STRIDE = K + 1;
    float* Xs = smem;                       // [256][K+1]
    float* Ws = smem + 256 * XS_STRIDE;     // [K][68]

    const int tid  = threadIdx.x;
    const int row0 = blockIdx.x * 256;

    for (int idx = tid; idx < 64 * K; idx += 256) {
        int j = idx / K;
        int k = idx - j * K;
        Ws[k * 68 + j] = W[idx];
    }
    for (int idx = tid; idx < 256 * K; idx += 256) {
        int r = idx / K;
        int k = idx - r * K;
        int gr = row0 + r;
        Xs[r * XS_STRIDE + k] = (gr < N) ? X[(size_t)gr * K + k] : 0.0f;
    }
    __syncthreads();

    const int cg = tid & 3;
    const int rg = tid >> 2;

    float acc[4][16];
#pragma unroll
    for (int i = 0; i < 4; ++i)
#pragma unroll
        for (int j = 0; j < 16; ++j) acc[i][j] = 0.0f;

    const float* wp = Ws + cg * 16;
    const float* xp = Xs + rg * 4 * XS_STRIDE;

#pragma unroll 4
    for (int k = 0; k < K; ++k) {
        float wv[16];
        *(float4*)(wv)      = *(const float4*)(wp + k * 68);
        *(float4*)(wv + 4)  = *(const float4*)(wp + k * 68 + 4);
        *(float4*)(wv + 8)  = *(const float4*)(wp + k * 68 + 8);
        *(float4*)(wv + 12) = *(const float4*)(wp + k * 68 + 12);
#pragma unroll
        for (int i = 0; i < 4; ++i) {
            float xv = xp[i * XS_STRIDE + k];
#pragma unroll
            for (int j = 0; j < 16; ++j) acc[i][j] += xv * wv[j];
        }
    }

    float bb[16];
    *(float4*)(bb)      = *(const float4*)(B + cg * 16);
    *(float4*)(bb + 4)  = *(const float4*)(B + cg * 16 + 4);
    *(float4*)(bb + 8)  = *(const float4*)(B + cg * 16 + 8);
    *(float4*)(bb + 12) = *(const float4*)(B + cg * 16 + 12);

#pragma unroll
    for (int i = 0; i < 4; ++i) {
        int gr = row0 + rg * 4 + i;
        if (gr >= N) continue;
        float o[16];
#pragma unroll
        for (int j = 0; j < 16; ++j) {
            float v = acc[i][j] + bb[j];
            o[j] = RELU ? (v > 0.0f ? v : 0.0f) : v;
        }
        if (sizeof(OutT) == 4) {
            float4* yp = (float4*)((float*)Y + (size_t)gr * 64 + cg * 16);
            yp[0] = *(float4*)(o);
            yp[1] = *(float4*)(o + 4);
            yp[2] = *(float4*)(o + 8);
            yp[3] = *(float4*)(o + 12);
        } else {
            __half2 hv[8];
#pragma unroll
            for (int j = 0; j < 8; ++j)
                hv[j] = __floats2half2_rn(o[2 * j], o[2 * j + 1]);
            uint4* yp = (uint4*)((__half*)Y + (size_t)gr * 64 + cg * 16);
            yp[0] = ((uint4*)hv)[0];
            yp[1] = ((uint4*)hv)[1];
        }
    }
}

// --------------------------- CSR build kernels -----------------------------
__global__ void hist_kernel(const int* __restrict__ dst, int E, int* __restrict__ cnt) {
    int e = blockIdx.x * blockDim.x + threadIdx.x;
    if (e < E) atomicAdd(&cnt[dst[e]], 1);
}

__global__ void scan_reduce_kernel(const int* __restrict__ cnt, int n,
                                   int* __restrict__ bsum) {
    __shared__ int sh[SCAN_CHUNK];
    int g = blockIdx.x * SCAN_CHUNK + threadIdx.x;
    int v = (g < n) ? cnt[g] : 0;
    sh[threadIdx.x] = v;
    __syncthreads();
    for (int off = SCAN_CHUNK / 2; off > 0; off >>= 1) {
        if (threadIdx.x < off) sh[threadIdx.x] += sh[threadIdx.x + off];
        __syncthreads();
    }
    if (threadIdx.x == 0) bsum[blockIdx.x] = sh[0];
}

__global__ void scan_partials_kernel(const int* __restrict__ bsum,
                                     int* __restrict__ boff,
                                     int* __restrict__ row, int n) {
    __shared__ int sh[256];
    int tid = threadIdx.x;
    int v = (tid < SCAN_NBLK) ? bsum[tid] : 0;
    sh[tid] = v;
    __syncthreads();
    for (int off = 1; off < 256; off <<= 1) {
        int t = (tid >= off) ? sh[tid - off] : 0;
        __syncthreads();
        sh[tid] += t;
        __syncthreads();
    }
    if (tid < SCAN_NBLK) boff[tid] = sh[tid] - v;   // exclusive
    if (tid == 255) row[n] = sh[255];               // total
}

__global__ void scan_final_kernel(const int* __restrict__ cnt, int n,
                                  const int* __restrict__ boff,
                                  int* __restrict__ row) {
    __shared__ int sh[SCAN_CHUNK];
    int tid = threadIdx.x;
    int g = blockIdx.x * SCAN_CHUNK + tid;
    int v = (g < n) ? cnt[g] : 0;
    sh[tid] = v;
    __syncthreads();
    for (int off = 1; off < SCAN_CHUNK; off <<= 1) {
        int t = (tid >= off) ? sh[tid - off] : 0;
        __syncthreads();
        sh[tid] += t;
        __syncthreads();
    }
    if (g < n) row[g] = boff[blockIdx.x] + sh[tid] - v;   // exclusive
}

__global__ void bin_kernel(const int* __restrict__ src, const int* __restrict__ dst,
                           int E, int base, int* __restrict__ cursor,
                           int* __restrict__ ssrc) {
    int e = blockIdx.x * blockDim.x + threadIdx.x;
    if (e >= E) return;
    int d = dst[e];
    int p = atomicAdd(&cursor[d], 1);
    ssrc[p] = src[e] + base;
}

// ---------------------------------------------------------------------------
// Gather-accumulate (fp16 messages, fp32 accumulation):
//   agg[n] = self[n] + sum_{e in CSR(n)} h_all[ssrc[e]]
// 16 threads per node; each lane covers 4 features (8 bytes fp16 per row).
// ---------------------------------------------------------------------------
__global__ void gather_kernel(const __half* __restrict__ h_all,
                              const float* __restrict__ self,
                              const int* __restrict__ row,
                              const int* __restrict__ ssrc,
                              float* __restrict__ agg) {
    int t = blockIdx.x * blockDim.x + threadIdx.x;
    int node = t >> 4;
    int lane = t & 15;
    if (node >= NX) return;
    float4 acc = ((const float4*)self)[(size_t)node * 16 + lane];
    int beg = row[node];
    int end = row[node + 1];
    const uint2* hp = (const uint2*)h_all;   // 4 halves per uint2; 16 per row
    for (int e = beg; e < end; ++e) {
        int s = ssrc[e];
        uint2 raw = hp[(size_t)s * 16 + lane];
        __half2 h0 = *(__half2*)&raw.x;
        __half2 h1 = *(__half2*)&raw.y;
        float2 f0 = __half22float2(h0);
        float2 f1 = __half22float2(h1);
        acc.x += f0.x; acc.y += f0.y; acc.z += f1.x; acc.w += f1.y;
    }
    ((float4*)agg)[(size_t)node * 16 + lane] = acc;
}

// ------------------------- stream/event singletons -------------------------
static cudaStream_t s_b = nullptr, s_c = nullptr;
static cudaEvent_t  ev_root = nullptr, ev_b = nullptr, ev_c = nullptr;

static void ensure_streams() {
    if (!s_b) {
        cudaStreamCreateWithFlags(&s_b, cudaStreamNonBlocking);
        cudaStreamCreateWithFlags(&s_c, cudaStreamNonBlocking);
        cudaEventCreateWithFlags(&ev_root, cudaEventDisableTiming);
        cudaEventCreateWithFlags(&ev_b,    cudaEventDisableTiming);
        cudaEventCreateWithFlags(&ev_c,    cudaEventDisableTiming);
    }
}

extern "C" void kernel_launch(void* const* d_in, const int* in_sizes, int n_in,
                              void* d_out, int out_size) {
    const float* x      = (const float*)d_in[0];
    const float* c      = (const float*)d_in[1];
    const float* r      = (const float*)d_in[2];
    const int* e_xx_s   = (const int*)d_in[3];
    const int* e_xx_d   = (const int*)d_in[4];
    const int* e_cx_s   = (const int*)d_in[5];
    const int* e_cx_d   = (const int*)d_in[6];
    const int* e_rx_s   = (const int*)d_in[7];
    const int* e_rx_d   = (const int*)d_in[8];
    const float* W_x    = (const float*)d_in[9];
    const float* b_x    = (const float*)d_in[10];
    const float* W_c    = (const float*)d_in[11];
    const float* b_c    = (const float*)d_in[12];
    const float* W_r    = (const float*)d_in[13];
    const float* b_r    = (const float*)d_in[14];
    const float* W_xx   = (const float*)d_in[15];
    const float* b_xx   = (const float*)d_in[16];
    const float* W_cx   = (const float*)d_in[17];
    const float* b_cx   = (const float*)d_in[18];
    const float* W_rx   = (const float*)d_in[19];
    const float* b_rx   = (const float*)d_in[20];
    const float* W_pool = (const float*)d_in[21];
    const float* b_pool = (const float*)d_in[22];
    float* out = (float*)d_out;

    const int E_xx = in_sizes[3];
    const int E_cx = in_sizes[5];
    const int E_rx = in_sizes[7];

    void* p;
    cudaGetSymbolAddress(&p, g_h_all); __half* h_all = (__half*)p;
    cudaGetSymbolAddress(&p, g_self);  float* hself = (float*)p;
    cudaGetSymbolAddress(&p, g_agg);   float* agg   = (float*)p;
    cudaGetSymbolAddress(&p, g_cnt);   int*   cnt   = (int*)p;
    cudaGetSymbolAddress(&p, g_row);   int*   row   = (int*)p;
    cudaGetSymbolAddress(&p, g_bsum);  int*   bsum  = (int*)p;
    cudaGetSymbolAddress(&p, g_boff);  int*   boff  = (int*)p;
    cudaGetSymbolAddress(&p, g_ssrc);  int*   ssrc  = (int*)p;

    ensure_streams();

    const int shb64 = (256 * 65 + 64 * 68) * 4;
    const int shb32 = (256 * 33 + 32 * 68) * 4;
    const int shb48 = (256 * 49 + 48 * 68) * 4;
    cudaFuncSetAttribute((const void*)linear_kernel<true, float>,
                         cudaFuncAttributeMaxDynamicSharedMemorySize, shb64);
    cudaFuncSetAttribute((const void*)linear_kernel<false, float>,
                         cudaFuncAttributeMaxDynamicSharedMemorySize, shb64);
    cudaFuncSetAttribute((const void*)linear_kernel<true, __half>,
                         cudaFuncAttributeMaxDynamicSharedMemorySize, shb64);

    const int OFF_C = NX * 64;
    const int OFF_R = NX * 64 + NC * 64;

    dim3 blk(256);
    int gx = (NX + 255) / 256;
    int gc = (NC + 255) / 256;
    int gr = (NR + 255) / 256;

    // ---- fork: root event on legacy stream ----
    cudaEventRecord(ev_root, 0);
    cudaStreamWaitEvent(s_b, ev_root, 0);
    cudaStreamWaitEvent(s_c, ev_root, 0);

    // ---- stream B: CSR build chain ----
    cudaMemsetAsync(cnt, 0, NX * sizeof(int), s_b);
    hist_kernel<<<(E_xx + 255) / 256, blk, 0, s_b>>>(e_xx_d, E_xx, cnt);
    hist_kernel<<<(E_cx + 255) / 256, blk, 0, s_b>>>(e_cx_d, E_cx, cnt);
    hist_kernel<<<(E_rx + 255) / 256, blk, 0, s_b>>>(e_rx_d, E_rx, cnt);
    scan_reduce_kernel<<<SCAN_NBLK, SCAN_CHUNK, 0, s_b>>>(cnt, NX, bsum);
    scan_partials_kernel<<<1, 256, 0, s_b>>>(bsum, boff, row, NX);
    scan_final_kernel<<<SCAN_NBLK, SCAN_CHUNK, 0, s_b>>>(cnt, NX, boff, row);
    cudaMemcpyAsync(cnt, row, NX * sizeof(int), cudaMemcpyDeviceToDevice, s_b);
    bin_kernel<<<(E_xx + 255) / 256, blk, 0, s_b>>>(e_xx_s, e_xx_d, E_xx, 0,       cnt, ssrc);
    bin_kernel<<<(E_cx + 255) / 256, blk, 0, s_b>>>(e_cx_s, e_cx_d, E_cx, NX,      cnt, ssrc);
    bin_kernel<<<(E_rx + 255) / 256, blk, 0, s_b>>>(e_rx_s, e_rx_d, E_rx, NX + NC, cnt, ssrc);
    cudaEventRecord(ev_b, s_b);

    // ---- stream C: c/r GEMMs ----
    linear_kernel<true, __half><<<gc, blk, shb32, s_c>>>(c, W_cx, b_cx, h_all + (size_t)NX*64, NC, 32);
    linear_kernel<true, __half><<<gr, blk, shb48, s_c>>>(r, W_rx, b_rx, h_all + (size_t)(NX+NC)*64, NR, 48);
    linear_kernel<true, float><<<gc, blk, shb32, s_c>>>(c, W_c,  b_c,  out + OFF_C, NC, 32);
    linear_kernel<true, float><<<gr, blk, shb48, s_c>>>(r, W_r,  b_r,  out + OFF_R, NR, 48);
    cudaEventRecord(ev_c, s_c);

    // ---- legacy stream: big x GEMMs ----
    linear_kernel<true, float><<<gx, blk, shb64>>>(x, W_x,  b_x,  hself, NX, 64);
    linear_kernel<true, __half><<<gx, blk, shb64>>>(x, W_xx, b_xx, h_all, NX, 64);

    // ---- join ----
    cudaStreamWaitEvent(0, ev_b, 0);
    cudaStreamWaitEvent(0, ev_c, 0);

    // ---- gather + pool (serial tail) ----
    {
        long long t = (long long)NX * 16;
        gather_kernel<<<(unsigned)((t + 255) / 256), blk>>>(h_all, hself, row, ssrc, agg);
    }
    linear_kernel<false, float><<<gx, blk, shb64>>>(agg, W_pool, b_pool, out, NX, 64);
}